// round 8
// baseline (speedup 1.0000x reference)
#include <cuda_runtime.h>
#include <math.h>

#define HID   2048
#define VOCAB 50257
#define NB    888               // 148 SMs x 6 blocks (co-resident by launch_bounds)
#define NT    256
#define NWARPS (NB * 8)         // 7104 warps grid-wide

// Scratch (no cudaMalloc allowed)
__device__ float        g_gi[3 * HID];
__device__ float        g_gh[3 * HID];
__device__ float        g_hnew[HID];
__device__ float        g_logits[VOCAB];
__device__ unsigned int g_max_u;
__device__ float        g_sum;
__device__ unsigned int g_bar;    // monotone grid-barrier counter
__device__ unsigned int g_done;   // end-of-kernel reset counter

// Grid barrier: all NB blocks co-resident (grid == exact residency capacity
// forced by __launch_bounds__(NT, 6)), so spinning is deadlock-free.
__device__ __forceinline__ void grid_barrier(unsigned int target)
{
    __syncthreads();
    if (threadIdx.x == 0) {
        __threadfence();                      // release this block's stores
        atomicAdd(&g_bar, 1u);
        volatile unsigned int* p = &g_bar;
        while (*p < target) { __nanosleep(32); }
        __threadfence();                      // acquire other blocks' stores
    }
    __syncthreads();
}

__global__ void __launch_bounds__(NT, 6) fused_kernel(
    const int*   __restrict__ idx,
    const float* __restrict__ hidden,
    const float* __restrict__ embed,
    const float* __restrict__ w_ih,
    const float* __restrict__ w_hh,
    const float* __restrict__ b_ih,
    const float* __restrict__ b_hh,
    const float* __restrict__ w_out,
    const float* __restrict__ b_out,
    float*       __restrict__ out,
    float*       __restrict__ hnew_out)   // may be null
{
    __shared__ float4 s_x[HID / 4];   // 8 KB: embed row (later reused for h_new)
    __shared__ float4 s_h[HID / 4];   // 8 KB: hidden
    __shared__ float  s_red[8];

    const int tid  = threadIdx.x;
    const int lane = tid & 31;
    const int warp = tid >> 5;
    const int bid  = blockIdx.x;

    // ---- stage x (embed row) and h into smem ----
    {
        const int token = idx[0];
        const float4* x4 = (const float4*)(embed + (size_t)token * HID);
        const float4* h4 = (const float4*)hidden;
        s_x[tid]       = x4[tid];
        s_x[tid + 256] = x4[tid + 256];
        s_h[tid]       = h4[tid];
        s_h[tid + 256] = h4[tid + 256];
    }
    __syncthreads();

    // ================= Phase 1: gate GEMVs (12288 virtual rows) ==========
    for (int vrow = bid * 8 + warp; vrow < 6 * HID; vrow += NWARPS) {
        const bool is_ih = vrow < 3 * HID;
        const int  row   = is_ih ? vrow : vrow - 3 * HID;
        const float4* w4 = (const float4*)((is_ih ? w_ih : w_hh) + (size_t)row * HID);
        const float4* sv = is_ih ? s_x : s_h;

        float acc = 0.0f;
        #pragma unroll
        for (int j = 0; j < 16; j++) {
            const int k = lane + 32 * j;
            const float4 w = w4[k];
            const float4 v = sv[k];
            acc += w.x*v.x + w.y*v.y + w.z*v.z + w.w*v.w;
        }
        #pragma unroll
        for (int o = 16; o; o >>= 1)
            acc += __shfl_xor_sync(0xffffffffu, acc, o);

        if (lane == 0) {
            if (is_ih) g_gi[row] = acc;
            else       g_gh[row] = acc;
        }
    }

    grid_barrier(1 * NB);

    // ================= Phase 2: elementwise gate math =====================
    {
        const int i = bid * NT + tid;          // first 8 blocks cover 0..2047
        if (i < HID) {
            const float gir = g_gi[i]         + b_ih[i];
            const float giz = g_gi[HID + i]   + b_ih[HID + i];
            const float gin = g_gi[2*HID + i] + b_ih[2*HID + i];
            const float ghr = g_gh[i]         + b_hh[i];
            const float ghz = g_gh[HID + i]   + b_hh[HID + i];
            const float ghn = g_gh[2*HID + i] + b_hh[2*HID + i];

            const float r  = 1.0f / (1.0f + expf(-(gir + ghr)));
            const float z  = 1.0f / (1.0f + expf(-(giz + ghz)));
            const float n  = tanhf(gin + r * ghn);
            const float hn = (1.0f - z) * n + z * hidden[i];

            g_hnew[i] = hn;
            if (hnew_out) hnew_out[i] = hn;
        }
        if (bid == 0 && tid == 0) { g_max_u = 0u; g_sum = 0.0f; }
    }

    grid_barrier(2 * NB);

    // ---- stage h_new into smem (reuse s_x) ----
    s_x[tid]       = ((const float4*)g_hnew)[tid];
    s_x[tid + 256] = ((const float4*)g_hnew)[tid + 256];
    __syncthreads();

    // ================= Phase 3: logits + running max ======================
    float lmax = 0.0f;
    for (int row = bid * 8 + warp; row < VOCAB; row += NWARPS) {
        const float4* w4 = (const float4*)(w_out + (size_t)row * HID);
        float acc = 0.0f;
        #pragma unroll
        for (int j = 0; j < 16; j++) {
            const int k = lane + 32 * j;
            const float4 w = w4[k];
            const float4 h = s_x[k];
            acc += w.x*h.x + w.y*h.y + w.z*h.z + w.w*h.w;
        }
        #pragma unroll
        for (int o = 16; o; o >>= 1)
            acc += __shfl_xor_sync(0xffffffffu, acc, o);
        if (lane == 0) {
            const float l = fmaxf(acc + b_out[row], 0.0f);
            g_logits[row] = l;
            lmax = fmaxf(lmax, l);
        }
    }
    #pragma unroll
    for (int o = 16; o; o >>= 1)
        lmax = fmaxf(lmax, __shfl_xor_sync(0xffffffffu, lmax, o));
    if (lane == 0) s_red[warp] = lmax;
    __syncthreads();
    if (tid == 0) {
        float m = s_red[0];
        #pragma unroll
        for (int w = 1; w < 8; w++) m = fmaxf(m, s_red[w]);
        atomicMax(&g_max_u, __float_as_uint(m));   // valid: all values >= 0
    }

    grid_barrier(3 * NB);

    // ================= Phase 4: sum of exp(l - max) =======================
    const float m = __uint_as_float(g_max_u);
    const int   v = bid * NT + tid;            // 227328 threads >= VOCAB
    float lv = 0.0f;
    float s  = 0.0f;
    if (v < VOCAB) {
        lv = g_logits[v];
        s  = expf(lv - m);
    }
    #pragma unroll
    for (int o = 16; o; o >>= 1)
        s += __shfl_xor_sync(0xffffffffu, s, o);
    if (lane == 0) s_red[warp] = s;
    __syncthreads();
    if (tid == 0) {
        float t = s_red[0];
        #pragma unroll
        for (int w = 1; w < 8; w++) t += s_red[w];
        if (t != 0.0f) atomicAdd(&g_sum, t);
    }

    grid_barrier(4 * NB);

    // ================= Phase 5: finalize ==================================
    if (v < VOCAB)
        out[v] = lv - m - logf(g_sum);

    // ---- reset barrier counters for the next graph replay ----
    __syncthreads();
    if (tid == 0) {
        if (atomicAdd(&g_done, 1u) == NB - 1u) {
            g_done = 0u;
            __threadfence();
            g_bar = 0u;
        }
    }
}

// ---------------------------------------------------------------------------
extern "C" void kernel_launch(void* const* d_in, const int* in_sizes, int n_in,
                              void* d_out, int out_size)
{
    const int*   idx    = (const int*)  d_in[0];
    const float* hidden = (const float*)d_in[1];
    const float* embed  = (const float*)d_in[2];
    const float* w_ih   = (const float*)d_in[3];
    const float* w_hh   = (const float*)d_in[4];
    const float* b_ih   = (const float*)d_in[5];
    const float* b_hh   = (const float*)d_in[6];
    const float* w_out  = (const float*)d_in[7];
    const float* b_out  = (const float*)d_in[8];

    float* out = (float*)d_out;
    float* hnew_out = (out_size >= VOCAB + HID) ? (out + VOCAB) : nullptr;

    fused_kernel<<<NB, NT>>>(idx, hidden, embed, w_ih, w_hh, b_ih, b_hh,
                             w_out, b_out, out, hnew_out);
}

// round 9
// speedup vs baseline: 1.6896x; 1.6896x over previous
#include <cuda_runtime.h>
#include <math.h>

#define HID   2048
#define VOCAB 50257

// Scratch (no cudaMalloc allowed). Static zero-init; counters self-reset.
__device__ float        g_part[2][6][HID];   // [half][gate-row][unit] partial dots
__device__ unsigned int g_unit_cnt[HID];     // per-unit arrival counters (0/1)
__device__ float        g_hnew[HID];
__device__ float        g_logits[VOCAB];
__device__ unsigned int g_max_u;
__device__ float        g_sum;
__device__ unsigned int g_count;             // softmax completion counter

// ---------------------------------------------------------------------------
// Kernel 1: GRU gate GEMVs, split-K x2. Block b -> (unit u = b>>1, half = b&1).
// Each block: 6 half-row dot products (rows u, H+u, 2H+u of w_ih and w_hh),
// 8 independent float4 loads per thread. Second arriver per unit combines
// partials, runs the gate math for that unit, resets the unit counter.
// ---------------------------------------------------------------------------
__global__ void __launch_bounds__(256, 6) gru_kernel(
    const int*   __restrict__ idx,
    const float* __restrict__ hidden,
    const float* __restrict__ embed,
    const float* __restrict__ w_ih,
    const float* __restrict__ w_hh,
    const float* __restrict__ b_ih,
    const float* __restrict__ b_hh,
    float*       __restrict__ hnew_out)   // may be null
{
    const int tid  = threadIdx.x;
    const int lane = tid & 31;
    const int warp = tid >> 5;
    const int u    = blockIdx.x >> 1;
    const int half = blockIdx.x & 1;

    const int token = idx[0];
    const int k = half * 256 + tid;        // float4 index within the row

    // 8 independent loads, front-batched.
    const float4 xv   = ((const float4*)(embed + (size_t)token * HID))[k];
    const float4 hv   = ((const float4*)hidden)[k];
    const float4 wi_r = ((const float4*)(w_ih + (size_t)( u         ) * HID))[k];
    const float4 wi_z = ((const float4*)(w_ih + (size_t)( HID   + u ) * HID))[k];
    const float4 wi_n = ((const float4*)(w_ih + (size_t)( 2*HID + u ) * HID))[k];
    const float4 wh_r = ((const float4*)(w_hh + (size_t)( u         ) * HID))[k];
    const float4 wh_z = ((const float4*)(w_hh + (size_t)( HID   + u ) * HID))[k];
    const float4 wh_n = ((const float4*)(w_hh + (size_t)( 2*HID + u ) * HID))[k];

    float a[6];
    a[0] = wi_r.x*xv.x + wi_r.y*xv.y + wi_r.z*xv.z + wi_r.w*xv.w;
    a[1] = wi_z.x*xv.x + wi_z.y*xv.y + wi_z.z*xv.z + wi_z.w*xv.w;
    a[2] = wi_n.x*xv.x + wi_n.y*xv.y + wi_n.z*xv.z + wi_n.w*xv.w;
    a[3] = wh_r.x*hv.x + wh_r.y*hv.y + wh_r.z*hv.z + wh_r.w*hv.w;
    a[4] = wh_z.x*hv.x + wh_z.y*hv.y + wh_z.z*hv.z + wh_z.w*hv.w;
    a[5] = wh_n.x*hv.x + wh_n.y*hv.y + wh_n.z*hv.z + wh_n.w*hv.w;

    #pragma unroll
    for (int o = 16; o; o >>= 1) {
        #pragma unroll
        for (int j = 0; j < 6; j++)
            a[j] += __shfl_xor_sync(0xffffffffu, a[j], o);
    }

    __shared__ float s[8][6];
    if (lane == 0) {
        #pragma unroll
        for (int j = 0; j < 6; j++) s[warp][j] = a[j];
    }
    __syncthreads();

    if (tid == 0) {
        float t[6];
        #pragma unroll
        for (int j = 0; j < 6; j++) {
            float v = s[0][j];
            #pragma unroll
            for (int w = 1; w < 8; w++) v += s[w][j];
            t[j] = v;
        }
        // Publish our partials, then arrive on the per-unit counter.
        #pragma unroll
        for (int j = 0; j < 6; j++) g_part[half][j][u] = t[j];
        __threadfence();                         // release partial stores
        const unsigned int prev = atomicAdd(&g_unit_cnt[u], 1u);

        if (prev == 1u) {                        // we're the second arriver
            __threadfence();                     // acquire partner's stores
            const int oh = 1 - half;
            const float gir = t[0] + g_part[oh][0][u] + b_ih[u];
            const float giz = t[1] + g_part[oh][1][u] + b_ih[HID + u];
            const float gin = t[2] + g_part[oh][2][u] + b_ih[2*HID + u];
            const float ghr = t[3] + g_part[oh][3][u] + b_hh[u];
            const float ghz = t[4] + g_part[oh][4][u] + b_hh[HID + u];
            const float ghn = t[5] + g_part[oh][5][u] + b_hh[2*HID + u];

            const float r  = 1.0f / (1.0f + expf(-(gir + ghr)));
            const float z  = 1.0f / (1.0f + expf(-(giz + ghz)));
            const float n  = tanhf(gin + r * ghn);
            const float hn = (1.0f - z) * n + z * hidden[u];

            g_hnew[u] = hn;
            if (hnew_out) hnew_out[u] = hn;

            g_unit_cnt[u] = 0u;                  // reset for next graph replay
            if (u == 0) { g_max_u = 0u; g_sum = 0.0f; g_count = 0u; }
        }
    }
}

// ---------------------------------------------------------------------------
// Kernel 2: logits = relu(w_out @ h_new + b_out). Warp-per-row, 8 rows/block.
// Tracks the global max via atomicMax on uint bits (valid: all values >= 0).
// ---------------------------------------------------------------------------
__global__ void __launch_bounds__(256) logits_kernel(
    const float* __restrict__ w_out,
    const float* __restrict__ b_out)
{
    const int lane = threadIdx.x & 31;
    const int warp = threadIdx.x >> 5;
    const int row  = blockIdx.x * 8 + warp;

    float l = 0.0f;
    if (row < VOCAB) {
        const float4* w4 = (const float4*)(w_out + (size_t)row * HID);
        const float4* h4 = (const float4*)g_hnew;
        float acc = 0.0f;
        #pragma unroll
        for (int j = 0; j < 16; j++) {
            const int k = lane + 32 * j;
            const float4 w = w4[k];
            const float4 h = h4[k];
            acc += w.x*h.x + w.y*h.y + w.z*h.z + w.w*h.w;
        }
        #pragma unroll
        for (int o = 16; o; o >>= 1)
            acc += __shfl_xor_sync(0xffffffffu, acc, o);
        l = fmaxf(acc + b_out[row], 0.0f);
        if (lane == 0) g_logits[row] = l;
    }

    __shared__ float smax[8];
    if (lane == 0) smax[warp] = l;
    __syncthreads();
    if (threadIdx.x == 0) {
        float m = smax[0];
        #pragma unroll
        for (int w = 1; w < 8; w++) m = fmaxf(m, smax[w]);
        atomicMax(&g_max_u, __float_as_uint(m));   // all values >= 0
    }
}

// ---------------------------------------------------------------------------
// Kernel 3: fused sum-exp + finalize. ONE wave (148 blocks x 256): partial
// sums -> atomicAdd -> completion-counter spin -> write outputs from regs.
// Safe: grid <= 1 block/SM, so all blocks are co-resident.
// ---------------------------------------------------------------------------
#define NBLK 148
#define ELEMS_PER_THREAD 2   // ceil(50257 / (148*256)) = 2

__global__ void __launch_bounds__(256) softmax_kernel(float* __restrict__ out)
{
    const int tid    = threadIdx.x;
    const int stride = NBLK * 256;
    const float m    = __uint_as_float(g_max_u);

    float lv[ELEMS_PER_THREAD];
    int   vi[ELEMS_PER_THREAD];
    float s = 0.0f;

    #pragma unroll
    for (int j = 0; j < ELEMS_PER_THREAD; j++) {
        const int v = blockIdx.x * 256 + tid + j * stride;
        vi[j] = v;
        if (v < VOCAB) {
            const float l = g_logits[v];
            lv[j] = l;
            s += expf(l - m);
        }
    }

    #pragma unroll
    for (int o = 16; o; o >>= 1)
        s += __shfl_xor_sync(0xffffffffu, s, o);

    __shared__ float sh[8];
    const int lane = tid & 31;
    const int warp = tid >> 5;
    if (lane == 0) sh[warp] = s;
    __syncthreads();

    if (tid == 0) {
        float t = sh[0];
        #pragma unroll
        for (int w = 1; w < 8; w++) t += sh[w];
        atomicAdd(&g_sum, t);
        __threadfence();
        atomicAdd(&g_count, 1u);
        volatile unsigned int* cnt = &g_count;
        while (*cnt < (unsigned int)gridDim.x) { __nanosleep(64); }
        __threadfence();
        sh[0] = logf(g_sum);
    }
    __syncthreads();

    const float logsum = sh[0];
    #pragma unroll
    for (int j = 0; j < ELEMS_PER_THREAD; j++) {
        if (vi[j] < VOCAB)
            out[vi[j]] = lv[j] - m - logsum;
    }
}

// ---------------------------------------------------------------------------
extern "C" void kernel_launch(void* const* d_in, const int* in_sizes, int n_in,
                              void* d_out, int out_size)
{
    const int*   idx    = (const int*)  d_in[0];
    const float* hidden = (const float*)d_in[1];
    const float* embed  = (const float*)d_in[2];
    const float* w_ih   = (const float*)d_in[3];
    const float* w_hh   = (const float*)d_in[4];
    const float* b_ih   = (const float*)d_in[5];
    const float* b_hh   = (const float*)d_in[6];
    const float* w_out  = (const float*)d_in[7];
    const float* b_out  = (const float*)d_in[8];

    float* out = (float*)d_out;
    float* hnew_out = (out_size >= VOCAB + HID) ? (out + VOCAB) : nullptr;

    gru_kernel<<<2 * HID, 256>>>(idx, hidden, embed, w_ih, w_hh,
                                 b_ih, b_hh, hnew_out);
    logits_kernel<<<(VOCAB + 7) / 8, 256>>>(w_out, b_out);
    softmax_kernel<<<NBLK, 256>>>(out);
}